// round 15
// baseline (speedup 1.0000x reference)
#include <cuda_runtime.h>
#include <cuda_fp16.h>
#include <cstdint>

// ======================= scratch (device globals) ==========================
__device__ __half g_p16[16384 * 256];         // im2col patches fp16
__device__ __half g_wc[1024 * 256];           // conv_w fp16 [N,K]
__device__ __half g_wt[4 * 1024 * 1024];      // Wq,Wk,Wv,Wp fp16 [N,K]
__device__ __half g_tok[16384 * 1024];        // tokens fp16
__device__ __half g_q16[16384 * 1024];        // q fp16, pre-scaled [B,H,T,D]
__device__ __half g_k16[16384 * 1024];        // k fp16 [B,H,T,D]
__device__ __half g_v16[16384 * 1024];        // v fp16 [B,H,T,D]
__device__ __half g_y16[16384 * 1024];        // attn out fp16 [B,T,C]
__device__ float  g_bqkv[3072];

// ======================= small helpers ======================================
__device__ __forceinline__ uint32_t smem_u32(const void* p) {
    uint32_t a;
    asm("{ .reg .u64 t; cvta.to.shared.u64 t, %1; cvt.u32.u64 %0, t; }"
        : "=r"(a) : "l"(p));
    return a;
}
__device__ __forceinline__ void cp_async16(uint32_t saddr, const void* gaddr) {
    asm volatile("cp.async.cg.shared.global [%0], [%1], 16;"
                 :: "r"(saddr), "l"(gaddr));
}
__device__ __forceinline__ void cp_commit() {
    asm volatile("cp.async.commit_group;");
}
__device__ __forceinline__ void cp_wait2() {
    asm volatile("cp.async.wait_group 2;");
}
__device__ __forceinline__ void ldsm_x4(uint32_t* r, uint32_t addr) {
    asm volatile("ldmatrix.sync.aligned.m8n8.x4.shared.b16 {%0,%1,%2,%3}, [%4];"
                 : "=r"(r[0]), "=r"(r[1]), "=r"(r[2]), "=r"(r[3]) : "r"(addr));
}
__device__ __forceinline__ void ldsm_x4_t(uint32_t* r, uint32_t addr) {
    asm volatile("ldmatrix.sync.aligned.m8n8.x4.trans.shared.b16 {%0,%1,%2,%3}, [%4];"
                 : "=r"(r[0]), "=r"(r[1]), "=r"(r[2]), "=r"(r[3]) : "r"(addr));
}
__device__ __forceinline__ void mma_f16(float4& d, const uint32_t a[4],
                                        uint32_t b0, uint32_t b1) {
    asm volatile(
        "mma.sync.aligned.m16n8k16.row.col.f32.f16.f16.f32 "
        "{%0,%1,%2,%3}, {%4,%5,%6,%7}, {%8,%9}, {%0,%1,%2,%3};"
        : "+f"(d.x), "+f"(d.y), "+f"(d.z), "+f"(d.w)
        : "r"(a[0]), "r"(a[1]), "r"(a[2]), "r"(a[3]), "r"(b0), "r"(b1));
}
__device__ __forceinline__ uint32_t swz64(uint32_t x) {
    return x ^ ((x >> 3) & 0x30);
}
__device__ __forceinline__ uint32_t pack_h2(float a, float b) {
    __half2 p = __floats2half2_rn(a, b);
    return *reinterpret_cast<uint32_t*>(&p);
}

// ======================= prep kernels =======================================
__global__ void im2col_h16(const float* __restrict__ x, __half* __restrict__ P) {
    int idx = blockIdx.x * 256 + threadIdx.x;
    int p = idx & 255, r = idx >> 8;
    int px = p & 15, py = p >> 4;
    int t = r & 255, b = r >> 8;
    int tx = t & 15, ty = t >> 4;
    float v = x[(size_t)b * 65536 + (size_t)(ty * 16 + py) * 256 + tx * 16 + px];
    P[idx] = __float2half_rn(v);
}

__global__ void cvt_elem(const float* __restrict__ W, __half* __restrict__ H) {
    int idx = blockIdx.x * 256 + threadIdx.x;
    H[idx] = __float2half_rn(W[idx]);
}

__global__ void wtrans_all(const float* __restrict__ W0, const float* __restrict__ W1,
                           const float* __restrict__ W2, const float* __restrict__ W3,
                           __half* __restrict__ T) {
    __shared__ float t[32][33];
    const int z = blockIdx.z;
    const float* W = (z == 0) ? W0 : (z == 1) ? W1 : (z == 2) ? W2 : W3;
    __half* th = T + (size_t)z * 1048576;
    int kb = blockIdx.x * 32, nb = blockIdx.y * 32;
    int x = threadIdx.x, y = threadIdx.y;  // 32 x 8
    #pragma unroll
    for (int i = 0; i < 32; i += 8)
        t[y + i][x] = W[(size_t)(kb + y + i) * 1024 + nb + x];
    __syncthreads();
    #pragma unroll
    for (int i = 0; i < 32; i += 8) {
        float v = t[x][y + i];
        int n = nb + y + i, k = kb + x;
        th[(size_t)n * 1024 + k] = __float2half_rn(v);
    }
}

__global__ void bias_concat(const float* __restrict__ bq, const float* __restrict__ bk,
                            const float* __restrict__ bv, float* __restrict__ dst) {
    int idx = blockIdx.x * 256 + threadIdx.x;  // 3072
    int which = idx >> 10, j = idx & 1023;
    dst[idx] = (which == 0) ? bq[j] : (which == 1) ? bk[j] : bv[j];
}

// ======================= fp16 1-term GEMM ===================================
// C = A[M,K] @ B^T (A, B single fp16; B stored [N,K]). fp32 accum.
// CTA tile 256x128 (512 threads, 16 warps, warp tile 32x64), BK=32,
// 4-stage cp.async (24KB/stage = 96KB), 1 CTA/SM (reg-file bound).
// Rationale: cp.async (LDGSTS) issue is the GEMM bottleneck; 256x128
// moves 683 MACs per 16B cp.async vs 512 at 128x128.
// mode 0: fp32 row-major + bias.
// mode 2: fp16 row-major + bias.
// mode 3: fused-qkv head layout: q -> fp16 scaled (Chi); k -> fp32 C + fp16 X1;
//         v -> fp32 C2 + fp16 X2.
__global__ void __launch_bounds__(512, 1) tc_gemm(
    const __half* __restrict__ A, const __half* __restrict__ B,
    const float* __restrict__ bias, float* __restrict__ C,
    float* __restrict__ C2,
    __half* __restrict__ Chi,
    __half* __restrict__ X1, __half* __restrict__ X2,
    int M, int N, int K, int mode)
{
    extern __shared__ char smem[];
    const uint32_t sb = smem_u32(smem);
    const int tid = threadIdx.x, wid = tid >> 5, lane = tid & 31;
    const int m0 = blockIdx.y * 256, n0 = blockIdx.x * 128;

    const uint32_t STG = 24576;   // A[0,16K) B[16K,24K); 4 stages

    const int row0 = tid >> 2;          // 0..127
    const int seg = tid & 3;
    const uint32_t soff0 = swz64(row0 * 64 + seg * 16);
    const uint32_t soff1 = swz64((row0 + 128) * 64 + seg * 16);

    const __half* A_g = A + (size_t)(m0 + row0) * K + seg * 8;
    const __half* B_g = B + (size_t)(n0 + row0) * K + seg * 8;
    const size_t rstep = (size_t)128 * K;

    const int NK = K >> 5;

    auto issue_stage = [&](int kt) {
        const uint32_t s = sb + (kt & 3) * STG;
        const size_t ko = (size_t)kt * 32;
        cp_async16(s + soff0,         A_g + ko);
        cp_async16(s + soff1,         A_g + ko + rstep);
        cp_async16(s + 16384 + soff0, B_g + ko);
    };

    issue_stage(0); cp_commit();
    issue_stage(1); cp_commit();
    issue_stage(2); cp_commit();

    // 16 warps: 8 m-tiles of 32 rows x 2 n-tiles of 64 cols
    const int wm = (wid & 7) * 32;
    const int wn = (wid >> 3) * 64;
    const int a_row = wm + (lane & 15);
    const int a_kb = (lane >> 4) * 16;
    const int b_row = wn + (lane & 7) + ((lane >> 4) & 1) * 8;
    const int b_kb = ((lane >> 3) & 1) * 16;

    float4 acc[2][8];
    #pragma unroll
    for (int i = 0; i < 2; i++)
        #pragma unroll
        for (int j = 0; j < 8; j++) acc[i][j] = make_float4(0.f, 0.f, 0.f, 0.f);

    for (int kt = 0; kt < NK; kt++) {
        cp_wait2();
        __syncthreads();
        if (kt + 3 < NK) issue_stage(kt + 3);
        cp_commit();

        const uint32_t s = sb + (kt & 3) * STG;

        auto boff = [&](int t) {
            return swz64((b_row + (t & 3) * 16) * 64 + (t >> 2) * 32 + b_kb);
        };

        uint32_t ah[2][2][4];      // [kb][mi]
        uint32_t br[3][4];         // B ring, prefetch distance 2

        #pragma unroll
        for (int mi = 0; mi < 2; mi++)
            ldsm_x4(ah[0][mi], s + swz64((a_row + mi * 16) * 64 + a_kb));
        ldsm_x4(br[0], s + 16384 + boff(0));
        ldsm_x4(br[1], s + 16384 + boff(1));

        #pragma unroll
        for (int t = 0; t < 8; t++) {
            const int kb = t >> 2, g = t & 3;
            if (t + 2 < 8) ldsm_x4(br[(t + 2) % 3], s + 16384 + boff(t + 2));
            if (t == 2) {
                #pragma unroll
                for (int mi = 0; mi < 2; mi++)
                    ldsm_x4(ah[1][mi],
                            s + swz64((a_row + mi * 16) * 64 + 32 + a_kb));
            }
            const uint32_t* bc = br[t % 3];
            mma_f16(acc[0][2 * g],     ah[kb][0], bc[0], bc[1]);
            mma_f16(acc[1][2 * g],     ah[kb][1], bc[0], bc[1]);
            mma_f16(acc[0][2 * g + 1], ah[kb][0], bc[2], bc[3]);
            mma_f16(acc[1][2 * g + 1], ah[kb][1], bc[2], bc[3]);
        }
    }

    // ---- epilogue ----
    const float qscale = 0.08838834764831845f;   // 1/sqrt(128)
    #pragma unroll
    for (int mi = 0; mi < 2; mi++) {
        const int ra = m0 + wm + mi * 16 + (lane >> 2);
        const int rb = ra + 8;
        #pragma unroll
        for (int ni = 0; ni < 8; ni++) {
            const int c = n0 + wn + ni * 8 + (lane & 3) * 2;
            const float bx = bias[c], by = bias[c + 1];
            float4 v = acc[mi][ni];
            v.x += bx; v.y += by; v.z += bx; v.w += by;
            if (mode == 0) {
                *(float2*)&C[(size_t)ra * N + c] = make_float2(v.x, v.y);
                *(float2*)&C[(size_t)rb * N + c] = make_float2(v.z, v.w);
            } else if (mode == 3) {
                const int which = c >> 10;
                const int cc = c & 1023;
                const int h = cc >> 7, d = cc & 127;
                const int ba_ = ra >> 8, ta = ra & 255;
                const int bb_ = rb >> 8, tb = rb & 255;
                const size_t oa = ((size_t)(ba_ * 8 + h) * 256 + ta) * 128 + d;
                const size_t ob = ((size_t)(bb_ * 8 + h) * 256 + tb) * 128 + d;
                if (which == 0) {
                    *(uint32_t*)&Chi[oa] = pack_h2(v.x * qscale, v.y * qscale);
                    *(uint32_t*)&Chi[ob] = pack_h2(v.z * qscale, v.w * qscale);
                } else {
                    float* base = (which == 1) ? C : C2;
                    __half* x16 = (which == 1) ? X1 : X2;
                    *(float2*)&base[oa] = make_float2(v.x, v.y);
                    *(float2*)&base[ob] = make_float2(v.z, v.w);
                    *(uint32_t*)&x16[oa] = pack_h2(v.x, v.y);
                    *(uint32_t*)&x16[ob] = pack_h2(v.z, v.w);
                }
            } else {
                *(uint32_t*)&Chi[(size_t)ra * N + c] = pack_h2(v.x, v.y);
                *(uint32_t*)&Chi[(size_t)rb * N + c] = pack_h2(v.z, v.w);
            }
        }
    }
}

// ======================= tensor-core causal attention =======================
// grid (512 bh, 2 q-halves), 256 threads (8 warps, 16 q-rows each = 128 rows).
// Q pre-scaled fp16 (1-term), K/V fp16, P fp16 (1-term). 3 CTAs/SM.
__global__ void __launch_bounds__(256) attn_mma(
    const __half* __restrict__ Q16,
    const __half* __restrict__ K16, const __half* __restrict__ V16,
    __half* __restrict__ Y16)
{
    extern __shared__ char smraw[];
    const uint32_t SQ = 0;              // 128 x 136 fp16 = 34816
    const uint32_t SK = 34816;          // 64 x 136 fp16 = 17408
    const uint32_t SV = 52224;          // 64 x 136 fp16 = 17408
    const uint32_t sb = smem_u32(smraw);

    const int bh = blockIdx.x;
    const int qh = 1 - blockIdx.y;      // heavy half (qh=1) scheduled first
    const int tid = threadIdx.x, wid = tid >> 5, lane = tid & 31;

    // ---- load Q half-tile (128 rows) ----
    const size_t qbase = ((size_t)bh * 256 + qh * 128) * 128;
    #pragma unroll
    for (int i = 0; i < 8; i++) {
        int e = tid + i * 256;          // 2048 segs of 8 fp16
        int row = e >> 4, sg = e & 15;
        *(uint4*)(smraw + SQ + row * 272 + sg * 16) =
            *(const uint4*)(Q16 + qbase + (size_t)row * 128 + sg * 8);
    }

    float4 o_[16];
    #pragma unroll
    for (int i = 0; i < 16; i++) o_[i] = make_float4(0.f, 0.f, 0.f, 0.f);
    float m0 = -1e30f, m1 = -1e30f, l0_ = 0.f, l1_ = 0.f;

    const int qr = wid * 16;                 // warp's row offset within Q tile
    const int qt_w = 2 * qh + (wid >> 2);    // warp's 64-row tile index
    const uint32_t a_off = ((qr + (lane & 15)) * 136 + (lane >> 4) * 8) * 2;
    const uint32_t bk_off = (((lane & 7) + ((lane >> 4) & 1) * 8) * 136 +
                             ((lane >> 3) & 1) * 8) * 2;
    const uint32_t bv_off = ((((lane >> 3) & 1) * 8 + (lane & 7)) * 136 +
                             (lane >> 4) * 8) * 2;

    const int njt = 2 * qh + 2;
    for (int jt = 0; jt < njt; jt++) {
        __syncthreads();
        const size_t tj = ((size_t)bh * 256 + jt * 64) * 128;
        #pragma unroll
        for (int i = 0; i < 4; i++) {
            int e = tid + i * 256;          // 1024 segs
            int row = e >> 4, sg = e & 15;
            uint32_t off = row * 272 + sg * 16;
            const size_t go = tj + (size_t)row * 128 + sg * 8;
            *(uint4*)(smraw + SK + off) = *(const uint4*)(K16 + go);
            *(uint4*)(smraw + SV + off) = *(const uint4*)(V16 + go);
        }
        __syncthreads();

        if (jt > qt_w) continue;   // fully masked for this warp

        // ---- S = Q K^T (1-term) ----
        float4 s[8];
        #pragma unroll
        for (int n = 0; n < 8; n++) s[n] = make_float4(0.f, 0.f, 0.f, 0.f);
        #pragma unroll
        for (int dk = 0; dk < 8; dk++) {
            uint32_t aq[4];
            ldsm_x4(aq, sb + SQ + a_off + dk * 32);
            #pragma unroll
            for (int np = 0; np < 4; np++) {
                uint32_t kh[4];
                uint32_t off = bk_off + (np * 16 * 136 + dk * 16) * 2;
                ldsm_x4(kh, sb + SK + off);
                mma_f16(s[2 * np],     aq, kh[0], kh[1]);
                mma_f16(s[2 * np + 1], aq, kh[2], kh[3]);
            }
        }

        if (jt == qt_w) {
            const int r0 = (wid & 3) * 16 + (lane >> 2), r1 = r0 + 8;
            #pragma unroll
            for (int n = 0; n < 8; n++) {
                int c = n * 8 + (lane & 3) * 2;
                if (c > r0) s[n].x = -1e30f;
                if (c + 1 > r0) s[n].y = -1e30f;
                if (c > r1) s[n].z = -1e30f;
                if (c + 1 > r1) s[n].w = -1e30f;
            }
        }

        // ---- online softmax ----
        float mx0 = -1e30f, mx1 = -1e30f;
        #pragma unroll
        for (int n = 0; n < 8; n++) {
            mx0 = fmaxf(mx0, fmaxf(s[n].x, s[n].y));
            mx1 = fmaxf(mx1, fmaxf(s[n].z, s[n].w));
        }
        mx0 = fmaxf(mx0, __shfl_xor_sync(0xffffffffu, mx0, 1));
        mx0 = fmaxf(mx0, __shfl_xor_sync(0xffffffffu, mx0, 2));
        mx1 = fmaxf(mx1, __shfl_xor_sync(0xffffffffu, mx1, 1));
        mx1 = fmaxf(mx1, __shfl_xor_sync(0xffffffffu, mx1, 2));
        const float mn0 = fmaxf(m0, mx0), mn1 = fmaxf(m1, mx1);
        const float al0 = __expf(m0 - mn0), al1 = __expf(m1 - mn1);
        float sum0 = 0.f, sum1 = 0.f;
        #pragma unroll
        for (int n = 0; n < 8; n++) {
            s[n].x = __expf(s[n].x - mn0); sum0 += s[n].x;
            s[n].y = __expf(s[n].y - mn0); sum0 += s[n].y;
            s[n].z = __expf(s[n].z - mn1); sum1 += s[n].z;
            s[n].w = __expf(s[n].w - mn1); sum1 += s[n].w;
        }
        sum0 += __shfl_xor_sync(0xffffffffu, sum0, 1);
        sum0 += __shfl_xor_sync(0xffffffffu, sum0, 2);
        sum1 += __shfl_xor_sync(0xffffffffu, sum1, 1);
        sum1 += __shfl_xor_sync(0xffffffffu, sum1, 2);
        l0_ = l0_ * al0 + sum0;
        l1_ = l1_ * al1 + sum1;
        m0 = mn0; m1 = mn1;
        #pragma unroll
        for (int i = 0; i < 16; i++) {
            o_[i].x *= al0; o_[i].y *= al0;
            o_[i].z *= al1; o_[i].w *= al1;
        }

        // ---- O += P V (1-term) ----
        #pragma unroll
        for (int kc = 0; kc < 4; kc++) {
            uint32_t pa[4];
            pa[0] = pack_h2(s[2 * kc].x,     s[2 * kc].y);
            pa[1] = pack_h2(s[2 * kc].z,     s[2 * kc].w);
            pa[2] = pack_h2(s[2 * kc + 1].x, s[2 * kc + 1].y);
            pa[3] = pack_h2(s[2 * kc + 1].z, s[2 * kc + 1].w);
            #pragma unroll
            for (int nd = 0; nd < 8; nd++) {
                uint32_t vh[4];
                uint32_t off = bv_off + (kc * 16 * 136 + nd * 16) * 2;
                ldsm_x4_t(vh, sb + SV + off);
                mma_f16(o_[2 * nd],     pa, vh[0], vh[1]);
                mma_f16(o_[2 * nd + 1], pa, vh[2], vh[3]);
            }
        }
    }

    // ---- write output (single fp16, [B,T,C] layout) ----
    const float inv0 = 1.0f / l0_, inv1 = 1.0f / l1_;
    const int b = bh >> 3, h = bh & 7;
    const int t0 = qh * 128 + qr + (lane >> 2), t1 = t0 + 8;
    const size_t base0 = ((size_t)(b * 256 + t0)) * 1024 + h * 128;
    const size_t base1 = ((size_t)(b * 256 + t1)) * 1024 + h * 128;
    #pragma unroll
    for (int nd = 0; nd < 16; nd++) {
        const int c = nd * 8 + (lane & 3) * 2;
        *(uint32_t*)&Y16[base0 + c] = pack_h2(o_[nd].x * inv0, o_[nd].y * inv0);
        *(uint32_t*)&Y16[base1 + c] = pack_h2(o_[nd].z * inv1, o_[nd].w * inv1);
    }
}

// ======================= launcher ===========================================
extern "C" void kernel_launch(void* const* d_in, const int* in_sizes, int n_in,
                              void* d_out, int out_size) {
    const float* x      = (const float*)d_in[0];
    const float* conv_w = (const float*)d_in[1];
    const float* conv_b = (const float*)d_in[2];
    const float* Wq     = (const float*)d_in[3];
    const float* bq     = (const float*)d_in[4];
    const float* Wk     = (const float*)d_in[5];
    const float* bk     = (const float*)d_in[6];
    const float* Wv     = (const float*)d_in[7];
    const float* bv     = (const float*)d_in[8];
    const float* Wp     = (const float*)d_in[9];
    const float* bp     = (const float*)d_in[10];
    float* out = (float*)d_out;

    const size_t YN = (size_t)64 * 256 * 1024;
    float* kout = out + YN;
    float* vout = out + 2 * YN;

    __half *p16, *wc, *wt, *tok, *q16, *k16, *v16, *y16;
    float* bqkv;
    cudaGetSymbolAddress((void**)&p16, g_p16);
    cudaGetSymbolAddress((void**)&wc, g_wc);
    cudaGetSymbolAddress((void**)&wt, g_wt);
    cudaGetSymbolAddress((void**)&tok, g_tok);
    cudaGetSymbolAddress((void**)&q16, g_q16);
    cudaGetSymbolAddress((void**)&k16, g_k16);
    cudaGetSymbolAddress((void**)&v16, g_v16);
    cudaGetSymbolAddress((void**)&y16, g_y16);
    cudaGetSymbolAddress((void**)&bqkv, g_bqkv);

    const int GEMM_SMEM = 4 * 24576;   // 98304
    cudaFuncSetAttribute(tc_gemm, cudaFuncAttributeMaxDynamicSharedMemorySize,
                         GEMM_SMEM);
    const int ATTN_SMEM = 34816 + 2 * 17408;   // 69632 -> 3 CTAs/SM
    cudaFuncSetAttribute(attn_mma, cudaFuncAttributeMaxDynamicSharedMemorySize,
                         ATTN_SMEM);

    // (1..3) prep needed by patch GEMM
    im2col_h16<<<16384, 256>>>(x, p16);
    cvt_elem<<<1024, 256>>>(conv_w, wc);
    wtrans_all<<<dim3(32, 32, 4), dim3(32, 8)>>>(Wq, Wk, Wv, Wp, wt);
    // (4) tok = patches @ conv_w^T + conv_b   <-- ncu capture slot
    tc_gemm<<<dim3(8, 64), 512, GEMM_SMEM>>>(p16, wc, conv_b,
                                             nullptr, nullptr,
                                             tok, nullptr, nullptr,
                                             16384, 1024, 256, 2);
    // (5) remaining prep
    bias_concat<<<12, 256>>>(bq, bk, bv, bqkv);
    // (6) fused qkv: q -> scaled fp16; k/v -> fp32 present + fp16
    tc_gemm<<<dim3(24, 64), 512, GEMM_SMEM>>>(tok, wt, bqkv,
                                              kout, vout, q16,
                                              k16, v16,
                                              16384, 3072, 1024, 3);
    // (7) attention (2 q-halves per bh, heavy half first)
    attn_mma<<<dim3(512, 2), 256, ATTN_SMEM>>>(q16, k16, v16, y16);
    // (8) y = yh @ Wp^T + bp
    tc_gemm<<<dim3(8, 64), 512, GEMM_SMEM>>>(y16, wt + 3 * 1048576,
                                             bp, out,
                                             nullptr,
                                             nullptr, nullptr, nullptr,
                                             16384, 1024, 1024, 0);
}